// round 3
// baseline (speedup 1.0000x reference)
#include <cuda_runtime.h>

#define NN 50000
#define NE 800000
#define FMAX 220

// ---------------- scratch (static device globals; no allocation) ------------
__device__ int   g_is64;           // 1 if edge_index is int64, 0 if int32
__device__ int   g_src[NE];
__device__ int   g_dst[NE];
__device__ int   g_deg_out[NN];
__device__ int   g_deg_in[NN];
__device__ float g_inv_out[NN];
__device__ float g_inv_in[NN];
__device__ int   g_rowptr[NN + 1];
__device__ int   g_cursor[NN];
__device__ int   g_col[NE];
__device__ float g_bufA[(size_t)NN * FMAX];
__device__ float g_bufB[(size_t)NN * FMAX];

// ---------------- dtype detection + conversion ------------------------------
// Read edge buffer as int32. If underlying data is int64 (values < NN), every
// odd 32-bit word is zero. If int32, odd words are random node ids.
__global__ void k_detect(const int* __restrict__ ei32) {
    if (threadIdx.x == 0) {
        int odd_nonzero = 0;
        for (int i = 0; i < 256; i++) {
            if (ei32[2 * i + 1] != 0) odd_nonzero++;
        }
        g_is64 = (odd_nonzero == 0) ? 1 : 0;
    }
}

__global__ void k_convert(const void* __restrict__ ei) {
    int e = blockIdx.x * blockDim.x + threadIdx.x;
    if (e >= NE) return;
    int s, d;
    if (g_is64) {
        const long long* p = (const long long*)ei;
        s = (int)p[e];
        d = (int)p[NE + e];
    } else {
        const int* p = (const int*)ei;
        s = p[e];
        d = p[NE + e];
    }
    g_src[e] = s;
    g_dst[e] = d;
}

// ---------------- graph prep ------------------------------------------------
__global__ void k_init_deg() {
    int i = blockIdx.x * blockDim.x + threadIdx.x;
    if (i < NN) { g_deg_out[i] = 0; g_deg_in[i] = 0; }
}

__global__ void k_degrees() {
    int e = blockIdx.x * blockDim.x + threadIdx.x;
    if (e < NE) {
        int s = g_src[e], d = g_dst[e];
        if ((unsigned)s < NN) atomicAdd(&g_deg_out[s], 1);
        if ((unsigned)d < NN) atomicAdd(&g_deg_in[d], 1);
    }
}

__global__ void k_invsqrt() {
    int i = blockIdx.x * blockDim.x + threadIdx.x;
    if (i < NN) {
        g_inv_out[i] = rsqrtf(fmaxf((float)g_deg_out[i], 1.0f));
        g_inv_in[i]  = rsqrtf(fmaxf((float)g_deg_in[i],  1.0f));
    }
}

// single-block exclusive scan of deg_in -> rowptr (and cursor copy)
__global__ void k_scan() {
    __shared__ int partial[1024];
    const int T = 1024;
    int t = threadIdx.x;
    const int chunk = (NN + T - 1) / T;  // 49
    int lo = t * chunk;
    int hi = min(lo + chunk, NN);
    int mysum = 0;
    for (int i = lo; i < hi; i++) mysum += g_deg_in[i];
    partial[t] = mysum;
    __syncthreads();
    // inclusive Hillis-Steele scan
    for (int off = 1; off < T; off <<= 1) {
        int v = (t >= off) ? partial[t - off] : 0;
        __syncthreads();
        partial[t] += v;
        __syncthreads();
    }
    int run = partial[t] - mysum;  // exclusive base for this thread
    for (int i = lo; i < hi; i++) {
        g_rowptr[i] = run;
        g_cursor[i] = run;
        run += g_deg_in[i];
    }
    if (t == 0) g_rowptr[NN] = partial[T - 1];
}

__global__ void k_fill() {
    int e = blockIdx.x * blockDim.x + threadIdx.x;
    if (e < NE) {
        int s = g_src[e];
        int d = g_dst[e];
        if ((unsigned)d < NN && (unsigned)s < NN) {
            int pos = atomicAdd(&g_cursor[d], 1);
            g_col[pos] = s;
        }
    }
}

// ---------------- aggregation: warp per dst node, CSR gather-reduce ---------
// out[n,:] = inv_in[n] * sum_{s in N_in(n)} (SCALE_SRC ? inv_out[s] : 1) * in[s,:]
//            (+ bias if ADD_BIAS)
template <int F, bool SCALE_SRC, bool ADD_BIAS>
__global__ void k_aggregate(const float* __restrict__ in, float* __restrict__ out,
                            const float* __restrict__ bias) {
    int warps_per_block = blockDim.x >> 5;
    int node = blockIdx.x * warps_per_block + (threadIdx.x >> 5);
    if (node >= NN) return;
    int lane = threadIdx.x & 31;
    constexpr int J = (F + 31) / 32;
    float acc[J];
#pragma unroll
    for (int j = 0; j < J; j++) acc[j] = 0.0f;

    int lo = g_rowptr[node];
    int hi = g_rowptr[node + 1];
    for (int e = lo; e < hi; e++) {
        int s = g_col[e];
        float sc = SCALE_SRC ? g_inv_out[s] : 1.0f;
        const float* row = in + (size_t)s * F;
#pragma unroll
        for (int j = 0; j < J; j++) {
            int f = lane + 32 * j;
            if (f < F) acc[j] += row[f] * sc;
        }
    }
    float oi = g_inv_in[node];
    float* orow = out + (size_t)node * F;
#pragma unroll
    for (int j = 0; j < J; j++) {
        int f = lane + 32 * j;
        if (f < F) {
            float v = acc[j] * oi;
            if (ADD_BIAS) v += bias[f];
            orow[f] = v;
        }
    }
}

// ---------------- SGEMM: C[M,N] = act(A[M,K] @ W[K,N] + bias) ---------------
// BM=128, BN=64, BK=16, 256 threads, 8x4 microtile.
// ROWSCALE multiplies A rows by g_inv_out at load.
template <bool TANH, bool ADD_BIAS, bool ROWSCALE>
__global__ void k_gemm(const float* __restrict__ A, const float* __restrict__ W,
                       const float* __restrict__ bias, float* __restrict__ C,
                       int M, int K, int N) {
    constexpr int BM = 128, BN = 64, BK = 16;
    __shared__ float As[BK][BM + 1];  // +1 pad: conflict-free transposed store
    __shared__ float Bs[BK][BN];

    int bm = blockIdx.y * BM;
    int bn = blockIdx.x * BN;
    int tid = threadIdx.x;           // 0..255
    int tr = tid >> 4;               // 0..15 -> 8 rows each
    int tc = tid & 15;               // 0..15 -> 4 cols each

    float acc[8][4];
#pragma unroll
    for (int i = 0; i < 8; i++)
#pragma unroll
        for (int j = 0; j < 4; j++) acc[i][j] = 0.0f;

    for (int k0 = 0; k0 < K; k0 += BK) {
        // load A tile (BM x BK), transposed into As[k][m]
#pragma unroll
        for (int i = 0; i < 8; i++) {
            int idx = tid + i * 256;     // 0..2047
            int m = idx >> 4;            // /BK
            int kk = idx & 15;
            int gm = bm + m, gk = k0 + kk;
            float v = 0.0f;
            if (gm < M && gk < K) {
                v = A[(size_t)gm * K + gk];
                if (ROWSCALE) v *= g_inv_out[gm];
            }
            As[kk][m] = v;
        }
        // load B tile (BK x BN)
#pragma unroll
        for (int i = 0; i < 4; i++) {
            int idx = tid + i * 256;     // 0..1023
            int kk = idx >> 6;           // /BN
            int n = idx & 63;
            int gk = k0 + kk, gn = bn + n;
            Bs[kk][n] = (gk < K && gn < N) ? W[(size_t)gk * N + gn] : 0.0f;
        }
        __syncthreads();
#pragma unroll
        for (int kk = 0; kk < BK; kk++) {
            float a[8], b[4];
#pragma unroll
            for (int i = 0; i < 8; i++) a[i] = As[kk][tr * 8 + i];
#pragma unroll
            for (int j = 0; j < 4; j++) b[j] = Bs[kk][tc * 4 + j];
#pragma unroll
            for (int i = 0; i < 8; i++)
#pragma unroll
                for (int j = 0; j < 4; j++) acc[i][j] += a[i] * b[j];
        }
        __syncthreads();
    }

#pragma unroll
    for (int i = 0; i < 8; i++) {
        int gm = bm + tr * 8 + i;
        if (gm >= M) continue;
#pragma unroll
        for (int j = 0; j < 4; j++) {
            int gn = bn + tc * 4 + j;
            if (gn >= N) continue;
            float v = acc[i][j];
            if (ADD_BIAS) v += bias[gn];
            if (TANH) v = tanhf(v);
            C[(size_t)gm * N + gn] = v;
        }
    }
}

// ---------------- launch -----------------------------------------------------
// Inputs resolved BY ELEMENT COUNT (robust to metadata ordering):
//   x=1,100,000 f32 | W0=4,840 | W1,W2=48,400 (in order) | W3=2,200
//   b0,b1,b2=220 (in order) | b3=10 | edge_index=1,600,000 (int32 OR int64;
//   dtype detected on-device)
extern "C" void kernel_launch(void* const* d_in, const int* in_sizes, int n_in,
                              void* d_out, int out_size) {
    const float* x  = nullptr;
    const float* W0 = nullptr; const float* W1 = nullptr;
    const float* W2 = nullptr; const float* W3 = nullptr;
    const float* b0 = nullptr; const float* b1 = nullptr;
    const float* b2 = nullptr; const float* b3 = nullptr;
    const void*  ei = nullptr;

    int n220 = 0, nbias = 0;
    for (int i = 0; i < n_in; i++) {
        int s = in_sizes[i];
        const void* p = d_in[i];
        switch (s) {
            case 1100000: x  = (const float*)p; break;
            case 4840:    W0 = (const float*)p; break;
            case 48400:   if (n220 == 0) W1 = (const float*)p;
                          else           W2 = (const float*)p;
                          n220++; break;
            case 2200:    W3 = (const float*)p; break;
            case 220:     if (nbias == 0) b0 = (const float*)p;
                          else if (nbias == 1) b1 = (const float*)p;
                          else b2 = (const float*)p;
                          nbias++; break;
            case 10:      b3 = (const float*)p; break;
            case 1600000: ei = p; break;
            default: break;
        }
    }
    float* out = (float*)d_out;

    float *bufA = nullptr, *bufB = nullptr;
    if (cudaGetSymbolAddress((void**)&bufA, g_bufA) != cudaSuccess) return;
    if (cudaGetSymbolAddress((void**)&bufB, g_bufB) != cudaSuccess) return;
    if (!x || !W0 || !W1 || !W2 || !W3 || !b0 || !b1 || !b2 || !b3 || !ei) return;

    const int TB = 256;
    // graph prep
    k_detect<<<1, 32>>>((const int*)ei);
    k_convert<<<(NE + TB - 1) / TB, TB>>>(ei);
    k_init_deg<<<(NN + TB - 1) / TB, TB>>>();
    k_degrees<<<(NE + TB - 1) / TB, TB>>>();
    k_invsqrt<<<(NN + TB - 1) / TB, TB>>>();
    k_scan<<<1, 1024>>>();
    k_fill<<<(NE + TB - 1) / TB, TB>>>();

    const int AGG_BLOCKS = (NN + 7) / 8;  // 8 warps/block
    dim3 gemm_grid((220 + 63) / 64, (NN + 127) / 128);
    dim3 gemm_grid3(1, (NN + 127) / 128);

    // Layer 0: agg(x, F=22) -> bufA ; gemm 22->220 +b0, tanh -> bufB
    k_aggregate<22, true, false><<<AGG_BLOCKS, TB>>>(x, bufA, nullptr);
    k_gemm<true, true, false><<<gemm_grid, TB>>>(bufA, W0, b0, bufB, NN, 22, 220);

    // Layer 1
    k_aggregate<220, true, false><<<AGG_BLOCKS, TB>>>(bufB, bufA, nullptr);
    k_gemm<true, true, false><<<gemm_grid, TB>>>(bufA, W1, b1, bufB, NN, 220, 220);

    // Layer 2
    k_aggregate<220, true, false><<<AGG_BLOCKS, TB>>>(bufB, bufA, nullptr);
    k_gemm<true, true, false><<<gemm_grid, TB>>>(bufA, W2, b2, bufB, NN, 220, 220);

    // Layer 3 (reordered): z = (h * inv_out) @ W3 -> bufA[N,10]; then aggregate
    // 10-wide with +b3 into out. (segment_sum commutes with @W: both linear.)
    k_gemm<false, false, true><<<gemm_grid3, TB>>>(bufB, W3, nullptr, bufA, NN, 220, 10);
    k_aggregate<10, false, true><<<AGG_BLOCKS, TB>>>(bufA, out, b3);
}

// round 6
// speedup vs baseline: 1.2749x; 1.2749x over previous
#include <cuda_runtime.h>
#include <cuda_bf16.h>
#include <cstdint>

#define NN 50000
#define NE 800000
#define FMAX 220

// ---------------- scratch (static device globals; no allocation) ------------
__device__ int   g_is64;           // 1 if edge_index is int64, 0 if int32
__device__ int   g_src[NE];
__device__ int   g_dst[NE];
__device__ int   g_deg_out[NN];
__device__ int   g_deg_in[NN];
__device__ float g_inv_out[NN];
__device__ float g_inv_in[NN];
__device__ int   g_rowptr[NN + 1];
__device__ int   g_cursor[NN];
__device__ int   g_col[NE];
__device__ __align__(16) float g_bufA[(size_t)NN * FMAX];
__device__ __align__(16) float g_bufB[(size_t)NN * FMAX];

// ---------------- dtype detection + conversion ------------------------------
__global__ void k_detect(const int* __restrict__ ei32) {
    if (threadIdx.x == 0) {
        int odd_nonzero = 0;
        for (int i = 0; i < 256; i++)
            if (ei32[2 * i + 1] != 0) odd_nonzero++;
        g_is64 = (odd_nonzero == 0) ? 1 : 0;
    }
}

__global__ void k_convert(const void* __restrict__ ei) {
    int e = blockIdx.x * blockDim.x + threadIdx.x;
    if (e >= NE) return;
    int s, d;
    if (g_is64) {
        const long long* p = (const long long*)ei;
        s = (int)p[e];
        d = (int)p[NE + e];
    } else {
        const int* p = (const int*)ei;
        s = p[e];
        d = p[NE + e];
    }
    g_src[e] = s;
    g_dst[e] = d;
}

// ---------------- graph prep ------------------------------------------------
__global__ void k_init_deg() {
    int i = blockIdx.x * blockDim.x + threadIdx.x;
    if (i < NN) { g_deg_out[i] = 0; g_deg_in[i] = 0; }
}

__global__ void k_degrees() {
    int e = blockIdx.x * blockDim.x + threadIdx.x;
    if (e < NE) {
        int s = g_src[e], d = g_dst[e];
        if ((unsigned)s < NN) atomicAdd(&g_deg_out[s], 1);
        if ((unsigned)d < NN) atomicAdd(&g_deg_in[d], 1);
    }
}

__global__ void k_invsqrt() {
    int i = blockIdx.x * blockDim.x + threadIdx.x;
    if (i < NN) {
        g_inv_out[i] = rsqrtf(fmaxf((float)g_deg_out[i], 1.0f));
        g_inv_in[i]  = rsqrtf(fmaxf((float)g_deg_in[i],  1.0f));
    }
}

__global__ void k_scan() {
    __shared__ int partial[1024];
    const int T = 1024;
    int t = threadIdx.x;
    const int chunk = (NN + T - 1) / T;
    int lo = t * chunk;
    int hi = min(lo + chunk, NN);
    int mysum = 0;
    for (int i = lo; i < hi; i++) mysum += g_deg_in[i];
    partial[t] = mysum;
    __syncthreads();
    for (int off = 1; off < T; off <<= 1) {
        int v = (t >= off) ? partial[t - off] : 0;
        __syncthreads();
        partial[t] += v;
        __syncthreads();
    }
    int run = partial[t] - mysum;
    for (int i = lo; i < hi; i++) {
        g_rowptr[i] = run;
        g_cursor[i] = run;
        run += g_deg_in[i];
    }
    if (t == 0) g_rowptr[NN] = partial[T - 1];
}

__global__ void k_fill() {
    int e = blockIdx.x * blockDim.x + threadIdx.x;
    if (e < NE) {
        int s = g_src[e];
        int d = g_dst[e];
        if ((unsigned)d < NN && (unsigned)s < NN) {
            int pos = atomicAdd(&g_cursor[d], 1);
            g_col[pos] = s;
        }
    }
}

// ---------------- aggregation (scalar, F small) -----------------------------
template <int F, bool SCALE_SRC, bool ADD_BIAS>
__global__ void k_aggregate(const float* __restrict__ in, float* __restrict__ out,
                            const float* __restrict__ bias) {
    int warps_per_block = blockDim.x >> 5;
    int node = blockIdx.x * warps_per_block + (threadIdx.x >> 5);
    if (node >= NN) return;
    int lane = threadIdx.x & 31;
    constexpr int J = (F + 31) / 32;
    float acc[J];
#pragma unroll
    for (int j = 0; j < J; j++) acc[j] = 0.0f;

    int lo = g_rowptr[node];
    int hi = g_rowptr[node + 1];
    for (int e = lo; e < hi; e++) {
        int s = g_col[e];
        float sc = SCALE_SRC ? g_inv_out[s] : 1.0f;
        const float* row = in + (size_t)s * F;
#pragma unroll
        for (int j = 0; j < J; j++) {
            int f = lane + 32 * j;
            if (f < F) acc[j] += row[f] * sc;
        }
    }
    float oi = g_inv_in[node];
    float* orow = out + (size_t)node * F;
#pragma unroll
    for (int j = 0; j < J; j++) {
        int f = lane + 32 * j;
        if (f < F) {
            float v = acc[j] * oi;
            if (ADD_BIAS) v += bias[f];
            orow[f] = v;
        }
    }
}

// ---------------- aggregation, F=220 vectorized (55 float4 per row) ---------
__global__ void k_aggregate220(const float* __restrict__ in, float* __restrict__ out) {
    int warps_per_block = blockDim.x >> 5;
    int node = blockIdx.x * warps_per_block + (threadIdx.x >> 5);
    if (node >= NN) return;
    int lane = threadIdx.x & 31;
    float4 acc0 = make_float4(0.f, 0.f, 0.f, 0.f);
    float4 acc1 = make_float4(0.f, 0.f, 0.f, 0.f);
    bool has1 = (lane + 32) < 55;

    int lo = g_rowptr[node];
    int hi = g_rowptr[node + 1];
    for (int e = lo; e < hi; e++) {
        int s = g_col[e];
        float sc = g_inv_out[s];
        const float4* row = (const float4*)(in + (size_t)s * 220);
        float4 v0 = row[lane];
        acc0.x += v0.x * sc; acc0.y += v0.y * sc;
        acc0.z += v0.z * sc; acc0.w += v0.w * sc;
        if (has1) {
            float4 v1 = row[lane + 32];
            acc1.x += v1.x * sc; acc1.y += v1.y * sc;
            acc1.z += v1.z * sc; acc1.w += v1.w * sc;
        }
    }
    float oi = g_inv_in[node];
    float4* orow = (float4*)(out + (size_t)node * 220);
    acc0.x *= oi; acc0.y *= oi; acc0.z *= oi; acc0.w *= oi;
    orow[lane] = acc0;
    if (has1) {
        acc1.x *= oi; acc1.y *= oi; acc1.z *= oi; acc1.w *= oi;
        orow[lane + 32] = acc1;
    }
}

// ---------------- tensor-core GEMM: split-bf16 (3 MMA) ----------------------
__device__ __forceinline__ void ldm_x4(uint32_t addr, uint32_t& r0, uint32_t& r1,
                                       uint32_t& r2, uint32_t& r3) {
    asm volatile("ldmatrix.sync.aligned.m8n8.x4.shared.b16 {%0,%1,%2,%3}, [%4];"
                 : "=r"(r0), "=r"(r1), "=r"(r2), "=r"(r3) : "r"(addr));
}

__device__ __forceinline__ void mma_bf16(float* c, const uint32_t* a, const uint32_t* b) {
    asm volatile(
        "mma.sync.aligned.m16n8k16.row.col.f32.bf16.bf16.f32 "
        "{%0,%1,%2,%3}, {%4,%5,%6,%7}, {%8,%9}, {%0,%1,%2,%3};"
        : "+f"(c[0]), "+f"(c[1]), "+f"(c[2]), "+f"(c[3])
        : "r"(a[0]), "r"(a[1]), "r"(a[2]), "r"(a[3]), "r"(b[0]), "r"(b[1]));
}

template <bool TANH>
__global__ void k_gemm_mma(const float* __restrict__ A, const float* __restrict__ W,
                           const float* __restrict__ bias, float* __restrict__ C,
                           int M, int K, int N) {
    constexpr int BM = 128, BN = 128, BK = 32, LDS = BK + 8;  // 80-byte rows
    __shared__ __nv_bfloat16 sAh[BM * LDS], sAl[BM * LDS];
    __shared__ __nv_bfloat16 sBh[BN * LDS], sBl[BN * LDS];

    int tid = threadIdx.x;
    int wid = tid >> 5, lane = tid & 31;
    int wm = wid >> 2, wn = wid & 3;  // 2 x 4 warp grid; warp tile 64x32
    int bm = blockIdx.y * BM, bn = blockIdx.x * BN;
    const bool kvec = (K % 4) == 0;   // float4 A loads only when rows 16B-aligned

    float acc[4][4][4];
#pragma unroll
    for (int i = 0; i < 4; i++)
#pragma unroll
        for (int j = 0; j < 4; j++)
#pragma unroll
            for (int t = 0; t < 4; t++) acc[i][j][t] = 0.0f;

    uint32_t sAh_b = (uint32_t)__cvta_generic_to_shared(sAh);
    uint32_t sAl_b = (uint32_t)__cvta_generic_to_shared(sAl);
    uint32_t sBh_b = (uint32_t)__cvta_generic_to_shared(sBh);
    uint32_t sBl_b = (uint32_t)__cvta_generic_to_shared(sBl);

    for (int k0 = 0; k0 < K; k0 += BK) {
        // ---- load A tile: BM x BK, fp32 -> bf16 hi/lo split ----
#pragma unroll
        for (int i = 0; i < 4; i++) {
            int idx = tid + i * 256;      // 0..1023
            int row = idx >> 3;           // /8 float4-groups per row
            int c4  = idx & 7;
            int gm = bm + row;
            int kb = k0 + c4 * 4;
            float v[4] = {0.f, 0.f, 0.f, 0.f};
            if (gm < M) {
                if (kvec && kb + 3 < K) {
                    float4 f = *(const float4*)(A + (size_t)gm * K + kb);
                    v[0] = f.x; v[1] = f.y; v[2] = f.z; v[3] = f.w;
                } else {
#pragma unroll
                    for (int j = 0; j < 4; j++)
                        if (kb + j < K) v[j] = A[(size_t)gm * K + kb + j];
                }
            }
#pragma unroll
            for (int j = 0; j < 4; j++) {
                __nv_bfloat16 h = __float2bfloat16(v[j]);
                __nv_bfloat16 l = __float2bfloat16(v[j] - __bfloat162float(h));
                sAh[row * LDS + c4 * 4 + j] = h;
                sAl[row * LDS + c4 * 4 + j] = l;
            }
        }
        // ---- load B tile: W[k0..k0+31][bn..bn+127] -> sB[n][k] ----
#pragma unroll
        for (int i = 0; i < 16; i++) {
            int idx = tid + i * 256;      // 0..4095
            int kk = idx >> 7;            // 0..31
            int n  = idx & 127;
            int gk = k0 + kk, gn = bn + n;
            float v = (gk < K && gn < N) ? W[(size_t)gk * N + gn] : 0.0f;
            __nv_bfloat16 h = __float2bfloat16(v);
            __nv_bfloat16 l = __float2bfloat16(v - __bfloat162float(h));
            sBh[n * LDS + kk] = h;
            sBl[n * LDS + kk] = l;
        }
        __syncthreads();

        // ---- compute: 2 k-steps of 16 ----
#pragma unroll
        for (int ks = 0; ks < 2; ks++) {
            int koff = ks * 16;
            uint32_t ah[4][4], al[4][4];
#pragma unroll
            for (int mf = 0; mf < 4; mf++) {
                int r = wm * 64 + mf * 16 + (lane & 15);
                uint32_t off = (uint32_t)(r * LDS + koff + ((lane >> 4) << 3)) * 2;
                ldm_x4(sAh_b + off, ah[mf][0], ah[mf][1], ah[mf][2], ah[mf][3]);
                ldm_x4(sAl_b + off, al[mf][0], al[mf][1], al[mf][2], al[mf][3]);
            }
            uint32_t bh[4][2], bl[4][2];
#pragma unroll
            for (int nf2 = 0; nf2 < 2; nf2++) {
                int n = wn * 32 + nf2 * 16 + (lane & 7) + ((lane & 16) >> 1);
                int kl = koff + (((lane >> 3) & 1) << 3);
                uint32_t off = (uint32_t)(n * LDS + kl) * 2;
                uint32_t r0, r1, r2, r3;
                ldm_x4(sBh_b + off, r0, r1, r2, r3);
                bh[nf2 * 2][0] = r0; bh[nf2 * 2][1] = r1;
                bh[nf2 * 2 + 1][0] = r2; bh[nf2 * 2 + 1][1] = r3;
                ldm_x4(sBl_b + off, r0, r1, r2, r3);
                bl[nf2 * 2][0] = r0; bl[nf2 * 2][1] = r1;
                bl[nf2 * 2 + 1][0] = r2; bl[nf2 * 2 + 1][1] = r3;
            }
#pragma unroll
            for (int mf = 0; mf < 4; mf++)
#pragma unroll
                for (int nf = 0; nf < 4; nf++) {
                    mma_bf16(acc[mf][nf], ah[mf], bh[nf]);
                    mma_bf16(acc[mf][nf], ah[mf], bl[nf]);
                    mma_bf16(acc[mf][nf], al[mf], bh[nf]);
                }
        }
        __syncthreads();
    }

    // ---- epilogue ----
#pragma unroll
    for (int mf = 0; mf < 4; mf++) {
        int r0 = bm + wm * 64 + mf * 16 + (lane >> 2);
        int r1 = r0 + 8;
#pragma unroll
        for (int nf = 0; nf < 4; nf++) {
            int col = bn + wn * 32 + nf * 8 + (lane & 3) * 2;
#pragma unroll
            for (int j = 0; j < 2; j++) {
                int gn = col + j;
                if (gn >= N) continue;
                float bb = bias ? bias[gn] : 0.0f;
                if (r0 < M) {
                    float v = acc[mf][nf][j] + bb;
                    if (TANH) v = tanhf(v);
                    C[(size_t)r0 * N + gn] = v;
                }
                if (r1 < M) {
                    float v = acc[mf][nf][2 + j] + bb;
                    if (TANH) v = tanhf(v);
                    C[(size_t)r1 * N + gn] = v;
                }
            }
        }
    }
}

// ---------------- fp32 SIMT GEMM (used for tiny layer 3) --------------------
template <bool TANH, bool ADD_BIAS, bool ROWSCALE>
__global__ void k_gemm(const float* __restrict__ A, const float* __restrict__ W,
                       const float* __restrict__ bias, float* __restrict__ C,
                       int M, int K, int N) {
    constexpr int BM = 128, BN = 64, BK = 16;
    __shared__ float As[BK][BM + 1];
    __shared__ float Bs[BK][BN];

    int bm = blockIdx.y * BM;
    int bn = blockIdx.x * BN;
    int tid = threadIdx.x;
    int tr = tid >> 4;
    int tc = tid & 15;

    float acc[8][4];
#pragma unroll
    for (int i = 0; i < 8; i++)
#pragma unroll
        for (int j = 0; j < 4; j++) acc[i][j] = 0.0f;

    for (int k0 = 0; k0 < K; k0 += BK) {
#pragma unroll
        for (int i = 0; i < 8; i++) {
            int idx = tid + i * 256;
            int m = idx >> 4;
            int kk = idx & 15;
            int gm = bm + m, gk = k0 + kk;
            float v = 0.0f;
            if (gm < M && gk < K) {
                v = A[(size_t)gm * K + gk];
                if (ROWSCALE) v *= g_inv_out[gm];
            }
            As[kk][m] = v;
        }
#pragma unroll
        for (int i = 0; i < 4; i++) {
            int idx = tid + i * 256;
            int kk = idx >> 6;
            int n = idx & 63;
            int gk = k0 + kk, gn = bn + n;
            Bs[kk][n] = (gk < K && gn < N) ? W[(size_t)gk * N + gn] : 0.0f;
        }
        __syncthreads();
#pragma unroll
        for (int kk = 0; kk < BK; kk++) {
            float a[8], b[4];
#pragma unroll
            for (int i = 0; i < 8; i++) a[i] = As[kk][tr * 8 + i];
#pragma unroll
            for (int j = 0; j < 4; j++) b[j] = Bs[kk][tc * 4 + j];
#pragma unroll
            for (int i = 0; i < 8; i++)
#pragma unroll
                for (int j = 0; j < 4; j++) acc[i][j] += a[i] * b[j];
        }
        __syncthreads();
    }

#pragma unroll
    for (int i = 0; i < 8; i++) {
        int gm = bm + tr * 8 + i;
        if (gm >= M) continue;
#pragma unroll
        for (int j = 0; j < 4; j++) {
            int gn = bn + tc * 4 + j;
            if (gn >= N) continue;
            float v = acc[i][j];
            if (ADD_BIAS) v += bias[gn];
            if (TANH) v = tanhf(v);
            C[(size_t)gm * N + gn] = v;
        }
    }
}

// ---------------- launch -----------------------------------------------------
extern "C" void kernel_launch(void* const* d_in, const int* in_sizes, int n_in,
                              void* d_out, int out_size) {
    const float* x  = nullptr;
    const float* W0 = nullptr; const float* W1 = nullptr;
    const float* W2 = nullptr; const float* W3 = nullptr;
    const float* b0 = nullptr; const float* b1 = nullptr;
    const float* b2 = nullptr; const float* b3 = nullptr;
    const void*  ei = nullptr;

    int n220 = 0, nbias = 0;
    for (int i = 0; i < n_in; i++) {
        int s = in_sizes[i];
        const void* p = d_in[i];
        switch (s) {
            case 1100000: x  = (const float*)p; break;
            case 4840:    W0 = (const float*)p; break;
            case 48400:   if (n220 == 0) W1 = (const float*)p;
                          else           W2 = (const float*)p;
                          n220++; break;
            case 2200:    W3 = (const float*)p; break;
            case 220:     if (nbias == 0) b0 = (const float*)p;
                          else if (nbias == 1) b1 = (const float*)p;
                          else b2 = (const float*)p;
                          nbias++; break;
            case 10:      b3 = (const float*)p; break;
            case 1600000: ei = p; break;
            default: break;
        }
    }
    float* out = (float*)d_out;

    float *bufA = nullptr, *bufB = nullptr;
    if (cudaGetSymbolAddress((void**)&bufA, g_bufA) != cudaSuccess) return;
    if (cudaGetSymbolAddress((void**)&bufB, g_bufB) != cudaSuccess) return;
    if (!x || !W0 || !W1 || !W2 || !W3 || !b0 || !b1 || !b2 || !b3 || !ei) return;

    const int TB = 256;
    // graph prep
    k_detect<<<1, 32>>>((const int*)ei);
    k_convert<<<(NE + TB - 1) / TB, TB>>>(ei);
    k_init_deg<<<(NN + TB - 1) / TB, TB>>>();
    k_degrees<<<(NE + TB - 1) / TB, TB>>>();
    k_invsqrt<<<(NN + TB - 1) / TB, TB>>>();
    k_scan<<<1, 1024>>>();
    k_fill<<<(NE + TB - 1) / TB, TB>>>();

    const int AGG_BLOCKS = (NN + 7) / 8;  // 8 warps/block
    dim3 mma_grid((220 + 127) / 128, (NN + 127) / 128);   // (2, 391)
    dim3 gemm_grid3(1, (NN + 127) / 128);

    // Layer 0: agg(x, F=22) -> bufA ; mma-gemm 22->220 +b0, tanh -> bufB
    k_aggregate<22, true, false><<<AGG_BLOCKS, TB>>>(x, bufA, nullptr);
    k_gemm_mma<true><<<mma_grid, TB>>>(bufA, W0, b0, bufB, NN, 22, 220);

    // Layer 1
    k_aggregate220<<<AGG_BLOCKS, TB>>>(bufB, bufA);
    k_gemm_mma<true><<<mma_grid, TB>>>(bufA, W1, b1, bufB, NN, 220, 220);

    // Layer 2
    k_aggregate220<<<AGG_BLOCKS, TB>>>(bufB, bufA);
    k_gemm_mma<true><<<mma_grid, TB>>>(bufA, W2, b2, bufB, NN, 220, 220);

    // Layer 3 (reordered): z = (h * inv_out) @ W3 -> bufA[N,10]; then aggregate
    // 10-wide with +b3 into out.
    k_gemm<false, false, true><<<gemm_grid3, TB>>>(bufB, W3, nullptr, bufA, NN, 220, 10);
    k_aggregate<10, false, true><<<AGG_BLOCKS, TB>>>(bufA, out, b3);
}